// round 14
// baseline (speedup 1.0000x reference)
#include <cuda_runtime.h>
#include <cuda_bf16.h>
#include <cstdint>

// Problem constants (shapes fixed by the dataset; sizes re-derived from in_sizes)
#define MAX_NODES 100000
#define IN_DIM    64
#define HID_DIM   32

// Scratch (allocation-free rule: __device__ globals).
// Device globals are zero-initialized at module load, and k_finalize re-zeros
// both degree arrays after consuming them, so every kernel_launch call
// (correctness run, graph capture, every replay) starts from zeroed counters.
__device__ int   g_deg_out[MAX_NODES];
__device__ int   g_deg_in [MAX_NODES];
__device__ float g_h      [MAX_NODES * HID_DIM];   // (X@W) * norm_src

// ---------------------------------------------------------------------------
// K1: out-degree histogram only (gates the gemm's norm_src).
//     4 edges/unit via int4 loads -> 4 independent REDGs in flight.
// ---------------------------------------------------------------------------
__global__ void k_hist_out(const int* __restrict__ src, int E) {
    int tid = blockIdx.x * blockDim.x + threadIdx.x;
    int gstride = gridDim.x * blockDim.x;
    int units = (E + 3) / 4;
    for (int u = tid; u < units; u += gstride) {
        int base = u * 4;
        if (base + 3 < E) {
            int4 s = __ldg(reinterpret_cast<const int4*>(src + base));
            atomicAdd(&g_deg_out[s.x], 1);
            atomicAdd(&g_deg_out[s.y], 1);
            atomicAdd(&g_deg_out[s.z], 1);
            atomicAdd(&g_deg_out[s.w], 1);
        } else {
            for (int i = base; i < E; i++)
                atomicAdd(&g_deg_out[__ldg(src + i)], 1);
        }
    }
}

// ---------------------------------------------------------------------------
// K2: gemm + src-norm, FUSED with out-zeroing and the in-degree histogram.
//     The gemm is DRAM-read bound (features 25.6MB); the zero stores ride the
//     idle write path and the deg_in REDGs ride the idle atomic pipe.
//     Ordering: zeroed out needed by K3, deg_in needed by K4 — both satisfied
//     by stream order after this kernel completes.
// ---------------------------------------------------------------------------
__global__ void k_gemm_fused(const float* __restrict__ X,
                             const float* __restrict__ W,
                             const int*   __restrict__ dst,
                             float4*      __restrict__ out4,
                             int n, int E) {
    __shared__ float sW[IN_DIM * HID_DIM];   // 8 KB
    for (int i = threadIdx.x; i < IN_DIM * HID_DIM; i += blockDim.x)
        sW[i] = W[i];
    __syncthreads();

    int tid = blockIdx.x * blockDim.x + threadIdx.x;
    int gstride = gridDim.x * blockDim.x;

    // --- absorbed work A: zero the output accumulator (d_out is poisoned) ---
    int tot4 = n * (HID_DIM / 4);
    float4 z = make_float4(0.f, 0.f, 0.f, 0.f);
    for (int i = tid; i < tot4; i += gstride)
        out4[i] = z;

    // --- absorbed work B: in-degree histogram (consumed only by finalize) ---
    int units = (E + 3) / 4;
    for (int u = tid; u < units; u += gstride) {
        int base = u * 4;
        if (base + 3 < E) {
            int4 d = __ldg(reinterpret_cast<const int4*>(dst + base));
            atomicAdd(&g_deg_in[d.x], 1);
            atomicAdd(&g_deg_in[d.y], 1);
            atomicAdd(&g_deg_in[d.z], 1);
            atomicAdd(&g_deg_in[d.w], 1);
        } else {
            for (int i = base; i < E; i++)
                atomicAdd(&g_deg_in[__ldg(dst + i)], 1);
        }
    }

    // --- main work: h = (X @ W) * rsqrt(max(deg_out,1)), one row/thread ---
    for (int r = tid; r < n; r += gstride) {
        float acc[HID_DIM];
#pragma unroll
        for (int j = 0; j < HID_DIM; j++) acc[j] = 0.f;

        const float4* xr = reinterpret_cast<const float4*>(X + (size_t)r * IN_DIM);
#pragma unroll 4
        for (int k4 = 0; k4 < IN_DIM / 4; k4++) {
            float4 x = __ldg(xr + k4);
            int k = k4 * 4;
#pragma unroll
            for (int j = 0; j < HID_DIM; j++) {
                acc[j] = fmaf(x.x, sW[(k + 0) * HID_DIM + j],
                         fmaf(x.y, sW[(k + 1) * HID_DIM + j],
                         fmaf(x.z, sW[(k + 2) * HID_DIM + j],
                         fmaf(x.w, sW[(k + 3) * HID_DIM + j], acc[j]))));
            }
        }

        float nrm = rsqrtf(fmaxf((float)g_deg_out[r], 1.0f));
        float4* hr = reinterpret_cast<float4*>(g_h + (size_t)r * HID_DIM);
#pragma unroll
        for (int j4 = 0; j4 < HID_DIM / 4; j4++) {
            float4 v;
            v.x = acc[j4 * 4 + 0] * nrm;
            v.y = acc[j4 * 4 + 1] * nrm;
            v.z = acc[j4 * 4 + 2] * nrm;
            v.w = acc[j4 * 4 + 3] * nrm;
            hr[j4] = v;
        }
    }
}

// ---------------------------------------------------------------------------
// K3: pure scatter  out[dst] += h[src].
//     8 threads / edge, one float4 each: coalesced 128B gather,
//     vector red.global.add.v4.f32. Sits at the REDG throughput floor.
// ---------------------------------------------------------------------------
__global__ void k_scatter(const int* __restrict__ src,
                          const int* __restrict__ dst,
                          float* __restrict__ out,
                          int E) {
    long long tid = (long long)blockIdx.x * blockDim.x + threadIdx.x;
    int e = (int)(tid >> 3);
    if (e >= E) return;
    int p = (int)(tid & 7);

    int s = __ldg(src + e);
    int d = __ldg(dst + e);

    float4 v = __ldg(reinterpret_cast<const float4*>(g_h + (size_t)s * HID_DIM) + p);
    float* addr = out + (size_t)d * HID_DIM + p * 4;

    asm volatile("red.global.add.v4.f32 [%0], {%1, %2, %3, %4};"
                 :: "l"(addr), "f"(v.x), "f"(v.y), "f"(v.z), "f"(v.w)
                 : "memory");
}

// ---------------------------------------------------------------------------
// K4: out = relu(out * rsqrt(max(deg_in,1)) + b)  (in place, 2 float4/thread
//     for MLP), + re-zero both degree arrays for the next launch.
// ---------------------------------------------------------------------------
__global__ void k_finalize(float4* __restrict__ out4,
                           const float* __restrict__ b,
                           int n) {
    __shared__ float4 sb[HID_DIM / 4];
    if (threadIdx.x < HID_DIM / 4)
        sb[threadIdx.x] = reinterpret_cast<const float4*>(b)[threadIdx.x];
    __syncthreads();

    int tot4 = n * (HID_DIM / 4);
    int half = (tot4 + 1) >> 1;                       // elements per slice
    int t = blockIdx.x * blockDim.x + threadIdx.x;
    if (t >= half) return;

    int i0 = t;
    int i1 = t + half;
    bool has1 = (i1 < tot4);

    int row0 = i0 >> 3, j40 = i0 & 7;
    int row1 = i1 >> 3, j41 = i1 & 7;

    // issue all independent loads first (MLP)
    float4 v0 = out4[i0];
    float4 v1 = has1 ? out4[i1] : make_float4(0.f, 0.f, 0.f, 0.f);
    int   di0 = g_deg_in[row0];
    int   di1 = has1 ? g_deg_in[row1] : 1;

    float nrm0 = rsqrtf(fmaxf((float)di0, 1.0f));
    float4 bb0 = sb[j40];
    v0.x = fmaxf(v0.x * nrm0 + bb0.x, 0.f);
    v0.y = fmaxf(v0.y * nrm0 + bb0.y, 0.f);
    v0.z = fmaxf(v0.z * nrm0 + bb0.z, 0.f);
    v0.w = fmaxf(v0.w * nrm0 + bb0.w, 0.f);
    out4[i0] = v0;

    if (has1) {
        float nrm1 = rsqrtf(fmaxf((float)di1, 1.0f));
        float4 bb1 = sb[j41];
        v1.x = fmaxf(v1.x * nrm1 + bb1.x, 0.f);
        v1.y = fmaxf(v1.y * nrm1 + bb1.y, 0.f);
        v1.z = fmaxf(v1.z * nrm1 + bb1.z, 0.f);
        v1.w = fmaxf(v1.w * nrm1 + bb1.w, 0.f);
        out4[i1] = v1;
    }

    // Reset counters for the next launch (one thread per row)
    if (j40 == 0) { g_deg_in[row0] = 0; g_deg_out[row0] = 0; }
    if (has1 && j41 == 0) { g_deg_in[row1] = 0; g_deg_out[row1] = 0; }
}

// ---------------------------------------------------------------------------
extern "C" void kernel_launch(void* const* d_in, const int* in_sizes, int n_in,
                              void* d_out, int out_size) {
    const float* features = (const float*)d_in[0];
    const int*   src      = (const int*)  d_in[1];
    const int*   dst      = (const int*)  d_in[2];
    const float* W        = (const float*)d_in[3];
    const float* b        = (const float*)d_in[4];
    float*       out      = (float*)d_out;

    int n = in_sizes[0] / IN_DIM;   // 100000
    int E = in_sizes[1];            // 1600000

    const int B = 256;

    // K1: out-degree histogram (gates gemm)
    k_hist_out<<<1184, B>>>(src, E);                  // 148 SMs x 8 CTAs

    // K2: gemm + src-norm, fused with out-zeroing + in-degree histogram
    k_gemm_fused<<<1184, B>>>(features, W, dst, (float4*)out, n, E);

    // K3: pure scatter (8 threads per edge)
    long long threads3 = (long long)E * 8;
    k_scatter<<<(int)((threads3 + B - 1) / B), B>>>(src, dst, out, E);

    // K4: finalize (2 float4/thread) + counter reset
    int tot4 = n * (HID_DIM / 4);
    int half = (tot4 + 1) >> 1;
    k_finalize<<<(half + B - 1) / B, B>>>((float4*)out, b, n);
}